// round 8
// baseline (speedup 1.0000x reference)
#include <cuda_runtime.h>
#include <cuda_fp16.h>
#include <cstdint>

// out[B,N] = x[B,K] @ w[K,N] + bias[N]
// fp16 HMMA m16n8k16 f32-accum. CTA 128x128, 4 warps (2x2), warp tile 64x64,
// 2 CTAs/SM. Register double-buffered fragments. Hybrid split-K tail:
// first 3*capacity tiles run full-K (3 exact waves); remainder tiles split
// into two K-halves merged by f32 atomics onto a bias-initialized output.
#define BATCH 4096
#define KDIM  4096
#define NDIM  4096

#define TM 128
#define TN 128
#define KC 64          // K elements per stage (128 bytes fp16 per row)
#define STAGES 3
#define THREADS 128    // 4 warps: 2 (M) x 2 (N), warp tile 64x64
#define K_ITERS (KDIM / KC)   // 64
#define NTILES ((BATCH / TM) * (NDIM / TN))   // 1024

// ---------------- scratch (device globals: allocation-free) ----------------
__device__ __half g_x[(size_t)BATCH * KDIM];
__device__ __half g_w[(size_t)NDIM * KDIM];   // transposed: [n][k]

// SMEM stage: A tile 128 rows x 128B, B tile 128 rows x 128B
#define STAGE_BYTES ((TM + TN) * 128)       // 32768
#define SMEM_TOTAL  (STAGES * STAGE_BYTES)  // 98304 (x2 CTAs = 192KB/SM)

__device__ __forceinline__ uint32_t smem_u32(const void* p) {
    uint32_t a;
    asm("{ .reg .u64 t; cvta.to.shared.u64 t, %1; cvt.u32.u64 %0, t; }"
        : "=r"(a) : "l"(p));
    return a;
}

__device__ __forceinline__ void cp_async16(uint32_t smaddr, const void* gptr) {
    asm volatile("cp.async.cg.shared.global [%0], [%1], 16;\n"
                 :: "r"(smaddr), "l"(gptr));
}
#define CP_COMMIT() asm volatile("cp.async.commit_group;\n" ::: "memory")
#define CP_WAIT1()  asm volatile("cp.async.wait_group 1;\n" ::: "memory")

__device__ __forceinline__ void ldsm_x4(uint32_t addr, uint32_t& r0, uint32_t& r1,
                                        uint32_t& r2, uint32_t& r3) {
    asm volatile("ldmatrix.sync.aligned.m8n8.x4.shared.b16 {%0,%1,%2,%3}, [%4];"
                 : "=r"(r0), "=r"(r1), "=r"(r2), "=r"(r3) : "r"(addr));
}

__device__ __forceinline__ void mma_16816(float* c, const uint32_t* a,
                                          uint32_t b0, uint32_t b1) {
    asm volatile(
        "mma.sync.aligned.m16n8k16.row.col.f32.f16.f16.f32 "
        "{%0,%1,%2,%3}, {%4,%5,%6,%7}, {%8,%9}, {%0,%1,%2,%3};"
        : "+f"(c[0]), "+f"(c[1]), "+f"(c[2]), "+f"(c[3])
        : "r"(a[0]), "r"(a[1]), "r"(a[2]), "r"(a[3]), "r"(b0), "r"(b1));
}

// ---------------- prepass 1: convert x -> fp16 ----------------
__global__ void __launch_bounds__(256) conv_x_kernel(const float4* __restrict__ x) {
    size_t i = (size_t)blockIdx.x * blockDim.x + threadIdx.x;  // 4 floats / thread
    float4 v = x[i];
    __half2* xp = reinterpret_cast<__half2*>(g_x);
    xp[2 * i]     = __floats2half2_rn(v.x, v.y);
    xp[2 * i + 1] = __floats2half2_rn(v.z, v.w);
}

// ---------------- prepass 2: transpose + convert w -> [n][k] fp16 ----------
__global__ void __launch_bounds__(256) conv_transpose_w_kernel(const float* __restrict__ w) {
    __shared__ float tile[32][33];
    int o0 = blockIdx.x * 32;  // output (N) tile
    int i0 = blockIdx.y * 32;  // input (K) tile
    int tx = threadIdx.x, ty = threadIdx.y;
    #pragma unroll
    for (int r = ty; r < 32; r += 8)
        tile[r][tx] = w[(size_t)(i0 + r) * NDIM + o0 + tx];
    __syncthreads();
    #pragma unroll
    for (int r = ty; r < 32; r += 8) {
        float f = tile[tx][r];  // = w[i0+tx][o0+r]
        g_w[(size_t)(o0 + r) * KDIM + i0 + tx] = __float2half_rn(f);
    }
}

// ---------------- bias-init for split-K remainder tiles ----------------
__global__ void __launch_bounds__(256) init_bias_kernel(const float* __restrict__ bias,
                                                        float* __restrict__ out,
                                                        int first_tile) {
    int tile = first_tile + blockIdx.x;
    int by = tile >> 5, bx = tile & 31;
    int tid = threadIdx.x;
    int c4 = (bx * TN) / 4 + (tid & 31);       // float4 column
    float4 bv = reinterpret_cast<const float4*>(bias)[c4];
    float4* op = reinterpret_cast<float4*>(out);
    #pragma unroll
    for (int i = 0; i < 16; ++i) {
        int row = by * TM + (tid >> 5) + i * 8;
        op[(size_t)row * (NDIM / 4) + c4] = bv;
    }
}

// ---------------- main GEMM ----------------
__global__ void __launch_bounds__(THREADS, 2)
gemm_fp16_kernel(const float* __restrict__ bias, float* __restrict__ out, int nfull) {
    extern __shared__ char smem[];
    uint32_t sb = smem_u32(smem);
    int tid = threadIdx.x;
    int lane = tid & 31;
    int wid = tid >> 5;
    int wm = wid & 1;       // M warp group: 64 rows
    int wn = wid >> 1;      // N warp group: 64 cols

    // decode tile / K-range / output mode
    int id = blockIdx.x;
    int tile, kbase, niter;
    bool full;
    if (id < nfull) {
        tile = id; kbase = 0; niter = K_ITERS; full = true;
    } else {
        int j = id - nfull;
        tile = nfull + (j >> 1);
        kbase = (j & 1) * (KDIM / 2);
        niter = K_ITERS / 2;
        full = false;
    }
    int m0 = (tile >> 5) * TM;
    int n0 = (tile & 31) * TN;

    float acc[4][8][4];     // [mt m16 tile][nb n8 tile][c0..c3]
    #pragma unroll
    for (int i = 0; i < 4; ++i)
        #pragma unroll
        for (int j = 0; j < 8; ++j)
            #pragma unroll
            for (int k = 0; k < 4; ++k) acc[i][j][k] = 0.f;

    // --- producer setup: per-thread fixed (row,seg); advance k per stage ---
    int prow = tid >> 3;          // 0..15
    int pseg = tid & 7;
    const __half* pA = g_x + (size_t)(m0 + prow) * KDIM + pseg * 8;
    const __half* pB = g_w + (size_t)(n0 + prow) * KDIM + pseg * 8;
    uint32_t soA[8], soB[8];
    #pragma unroll
    for (int j = 0; j < 8; ++j) {
        int rowA = prow + j * 16;
        soA[j] = rowA * 128 + ((pseg ^ (rowA & 7)) << 4);
        soB[j] = TM * 128 + rowA * 128 + ((pseg ^ (rowA & 7)) << 4);
    }

    #define LOAD_STAGE_PART(sa_, kk_, j0_, j1_)                                   \
        _Pragma("unroll")                                                          \
        for (int j = (j0_); j < (j1_); ++j) {                                      \
            if (j < 8) cp_async16((sa_) + soA[j], pA + (size_t)j * 16 * KDIM + (kk_)); \
            else       cp_async16((sa_) + soB[j - 8], pB + (size_t)(j - 8) * 16 * KDIM + (kk_)); \
        }

    // prologue: stages 0 and 1
    LOAD_STAGE_PART(sb + 0 * STAGE_BYTES, kbase + 0 * KC, 0, 16); CP_COMMIT();
    LOAD_STAGE_PART(sb + 1 * STAGE_BYTES, kbase + 1 * KC, 0, 16); CP_COMMIT();

    int la = (lane & 15);
    int khalf = lane >> 4;

    // fragment double buffers
    uint32_t afb[2][4][4];
    uint32_t bfb[2][8][2];

    #define LOAD_FRAGS(sa_, sB_, ks_, buf_) do {                                  \
        int seg_ = 2 * (ks_) + khalf;                                             \
        _Pragma("unroll")                                                          \
        for (int q = 0; q < 4; ++q) {                                             \
            int row_ = wn * 64 + q * 16 + la;                                     \
            uint32_t addr_ = (sB_) + row_ * 128 + ((seg_ ^ (row_ & 7)) << 4);     \
            uint32_t r0_, r1_, r2_, r3_;                                          \
            ldsm_x4(addr_, r0_, r1_, r2_, r3_);                                   \
            bfb[buf_][2 * q][0] = r0_;     bfb[buf_][2 * q][1] = r2_;             \
            bfb[buf_][2 * q + 1][0] = r1_; bfb[buf_][2 * q + 1][1] = r3_;         \
        }                                                                          \
        _Pragma("unroll")                                                          \
        for (int mt = 0; mt < 4; ++mt) {                                          \
            int row_ = wm * 64 + mt * 16 + la;                                    \
            uint32_t addr_ = (sa_) + row_ * 128 + ((seg_ ^ (row_ & 7)) << 4);     \
            ldsm_x4(addr_, afb[buf_][mt][0], afb[buf_][mt][1],                    \
                    afb[buf_][mt][2], afb[buf_][mt][3]);                          \
        }                                                                          \
    } while (0)

    int cons = 0, prod = 2;   // stage indices
    for (int it = 0; it < niter; ++it) {
        CP_WAIT1();
        __syncthreads();

        uint32_t sa = sb + cons * STAGE_BYTES;
        uint32_t sB = sa + TM * 128;
        uint32_t sp = sb + prod * STAGE_BYTES;
        bool do_load = (it + 2 < niter);
        int kp = kbase + (it + 2) * KC;

        LOAD_FRAGS(sa, sB, 0, 0);

        #pragma unroll
        for (int ks = 0; ks < 4; ++ks) {
            int buf = ks & 1;
            if (ks < 3) LOAD_FRAGS(sa, sB, ks + 1, buf ^ 1);
            if (do_load) LOAD_STAGE_PART(sp, kp, ks * 4, ks * 4 + 4);
            #pragma unroll
            for (int mt = 0; mt < 4; ++mt)
                #pragma unroll
                for (int nb = 0; nb < 8; ++nb)
                    mma_16816(acc[mt][nb], afb[buf][mt],
                              bfb[buf][nb][0], bfb[buf][nb][1]);
        }
        CP_COMMIT();

        cons = (cons == STAGES - 1) ? 0 : cons + 1;
        prod = (prod == STAGES - 1) ? 0 : prod + 1;
    }

    // ---------------- epilogue ----------------
    if (full) {
        float2 bv[8];
        #pragma unroll
        for (int nb = 0; nb < 8; ++nb) {
            int col = n0 + wn * 64 + nb * 8 + (lane & 3) * 2;
            bv[nb] = *reinterpret_cast<const float2*>(bias + col);
        }
        #pragma unroll
        for (int mt = 0; mt < 4; ++mt) {
            int gr = m0 + wm * 64 + mt * 16 + (lane >> 2);
            float* r0p = out + (size_t)gr * NDIM;
            float* r1p = r0p + 8 * (size_t)NDIM;
            #pragma unroll
            for (int nb = 0; nb < 8; ++nb) {
                int col = n0 + wn * 64 + nb * 8 + (lane & 3) * 2;
                float2 v0 = make_float2(acc[mt][nb][0] + bv[nb].x,
                                        acc[mt][nb][1] + bv[nb].y);
                float2 v1 = make_float2(acc[mt][nb][2] + bv[nb].x,
                                        acc[mt][nb][3] + bv[nb].y);
                *reinterpret_cast<float2*>(r0p + col) = v0;
                *reinterpret_cast<float2*>(r1p + col) = v1;
            }
        }
    } else {
        // split-K half: reduce onto bias-initialized output
        #pragma unroll
        for (int mt = 0; mt < 4; ++mt) {
            int gr = m0 + wm * 64 + mt * 16 + (lane >> 2);
            float* r0p = out + (size_t)gr * NDIM;
            float* r1p = r0p + 8 * (size_t)NDIM;
            #pragma unroll
            for (int nb = 0; nb < 8; ++nb) {
                int col = n0 + wn * 64 + nb * 8 + (lane & 3) * 2;
                atomicAdd(r0p + col,     acc[mt][nb][0]);
                atomicAdd(r0p + col + 1, acc[mt][nb][1]);
                atomicAdd(r1p + col,     acc[mt][nb][2]);
                atomicAdd(r1p + col + 1, acc[mt][nb][3]);
            }
        }
    }
}

// ---------------- launch ----------------
extern "C" void kernel_launch(void* const* d_in, const int* in_sizes, int n_in,
                              void* d_out, int out_size) {
    const float* x    = (const float*)d_in[0];
    const float* w    = (const float*)d_in[1];
    const float* bias = (const float*)d_in[2];
    float* out = (float*)d_out;

    int dev = 0, smCount = 148;
    cudaGetDevice(&dev);
    cudaDeviceGetAttribute(&smCount, cudaDevAttrMultiProcessorCount, dev);
    int cap = 2 * smCount;                 // 2 CTAs/SM resident
    int nfull = 3 * cap;                   // exactly 3 full waves
    if (nfull > NTILES) nfull = NTILES;
    int nrem = NTILES - nfull;

    conv_x_kernel<<<(BATCH * (size_t)KDIM / 4) / 256, 256>>>((const float4*)x);
    conv_transpose_w_kernel<<<dim3(NDIM / 32, KDIM / 32), dim3(32, 8)>>>(w);
    if (nrem > 0)
        init_bias_kernel<<<nrem, 256>>>(bias, out, nfull);

    cudaFuncSetAttribute(gemm_fp16_kernel,
                         cudaFuncAttributeMaxDynamicSharedMemorySize, SMEM_TOTAL);
    gemm_fp16_kernel<<<nfull + 2 * nrem, THREADS, SMEM_TOTAL>>>(bias, out, nfull);
}

// round 9
// speedup vs baseline: 1.0450x; 1.0450x over previous
#include <cuda_runtime.h>
#include <cuda_fp16.h>
#include <cstdint>

// out[B,N] = x[B,K] @ w[K,N] + bias[N]
// fp16 HMMA m16n8k16 f32-accum. CTA 128x128, 4 warps (2x2), warp tile 64x64,
// 2 CTAs/SM. Register double-buffered fragments. Mainloop unrolled by 3 so
// all SMEM stage bases are compile-time immediates (kills address-ALU load).
#define BATCH 4096
#define KDIM  4096
#define NDIM  4096

#define TM 128
#define TN 128
#define KC 64          // K elements per stage (128 bytes fp16 per row)
#define STAGES 3
#define THREADS 128    // 4 warps: 2 (M) x 2 (N), warp tile 64x64
#define K_ITERS (KDIM / KC)   // 64

// ---------------- scratch (device globals: allocation-free) ----------------
__device__ __half g_x[(size_t)BATCH * KDIM];
__device__ __half g_w[(size_t)NDIM * KDIM];   // transposed: [n][k]

#define STAGE_BYTES ((TM + TN) * 128)       // 32768
#define SMEM_TOTAL  (STAGES * STAGE_BYTES)  // 98304 (x2 CTAs = 192KB/SM)

__device__ __forceinline__ uint32_t smem_u32(const void* p) {
    uint32_t a;
    asm("{ .reg .u64 t; cvta.to.shared.u64 t, %1; cvt.u32.u64 %0, t; }"
        : "=r"(a) : "l"(p));
    return a;
}

__device__ __forceinline__ void cp_async16(uint32_t smaddr, const void* gptr) {
    asm volatile("cp.async.cg.shared.global [%0], [%1], 16;\n"
                 :: "r"(smaddr), "l"(gptr));
}
#define CP_COMMIT() asm volatile("cp.async.commit_group;\n" ::: "memory")
#define CP_WAIT1()  asm volatile("cp.async.wait_group 1;\n" ::: "memory")

__device__ __forceinline__ void ldsm_x4(uint32_t addr, uint32_t& r0, uint32_t& r1,
                                        uint32_t& r2, uint32_t& r3) {
    asm volatile("ldmatrix.sync.aligned.m8n8.x4.shared.b16 {%0,%1,%2,%3}, [%4];"
                 : "=r"(r0), "=r"(r1), "=r"(r2), "=r"(r3) : "r"(addr));
}

__device__ __forceinline__ void mma_16816(float* c, const uint32_t* a,
                                          uint32_t b0, uint32_t b1) {
    asm volatile(
        "mma.sync.aligned.m16n8k16.row.col.f32.f16.f16.f32 "
        "{%0,%1,%2,%3}, {%4,%5,%6,%7}, {%8,%9}, {%0,%1,%2,%3};"
        : "+f"(c[0]), "+f"(c[1]), "+f"(c[2]), "+f"(c[3])
        : "r"(a[0]), "r"(a[1]), "r"(a[2]), "r"(a[3]), "r"(b0), "r"(b1));
}

// ---------------- prepass 1: convert x -> fp16 ----------------
__global__ void __launch_bounds__(256) conv_x_kernel(const float4* __restrict__ x) {
    size_t i = (size_t)blockIdx.x * blockDim.x + threadIdx.x;  // 4 floats / thread
    float4 v = x[i];
    __half2* xp = reinterpret_cast<__half2*>(g_x);
    xp[2 * i]     = __floats2half2_rn(v.x, v.y);
    xp[2 * i + 1] = __floats2half2_rn(v.z, v.w);
}

// ---------------- prepass 2: transpose + convert w -> [n][k] fp16 ----------
__global__ void __launch_bounds__(256) conv_transpose_w_kernel(const float* __restrict__ w) {
    __shared__ float tile[32][33];
    int o0 = blockIdx.x * 32;  // output (N) tile
    int i0 = blockIdx.y * 32;  // input (K) tile
    int tx = threadIdx.x, ty = threadIdx.y;
    #pragma unroll
    for (int r = ty; r < 32; r += 8)
        tile[r][tx] = w[(size_t)(i0 + r) * NDIM + o0 + tx];
    __syncthreads();
    #pragma unroll
    for (int r = ty; r < 32; r += 8) {
        float f = tile[tx][r];  // = w[i0+tx][o0+r]
        g_w[(size_t)(o0 + r) * KDIM + i0 + tx] = __float2half_rn(f);
    }
}

// ---------------- main GEMM ----------------
__global__ void __launch_bounds__(THREADS, 2)
gemm_fp16_kernel(const float* __restrict__ bias, float* __restrict__ out) {
    extern __shared__ char smem[];
    uint32_t sb = smem_u32(smem);
    int tid = threadIdx.x;
    int lane = tid & 31;
    int wid = tid >> 5;
    int wm = wid & 1;       // M warp group: 64 rows
    int wn = wid >> 1;      // N warp group: 64 cols
    int m0 = blockIdx.y * TM;
    int n0 = blockIdx.x * TN;

    float acc[4][8][4];     // [mt m16 tile][nb n8 tile][c0..c3]
    #pragma unroll
    for (int i = 0; i < 4; ++i)
        #pragma unroll
        for (int j = 0; j < 8; ++j)
            #pragma unroll
            for (int k = 0; k < 4; ++k) acc[i][j][k] = 0.f;

    // --- producer: per-thread fixed (row,seg); two pointers advance by KC ---
    int prow = tid >> 3;          // 0..15
    int pseg = tid & 7;
    const __half* pAk = g_x + (size_t)(m0 + prow) * KDIM + pseg * 8;
    const __half* pBk = g_w + (size_t)(n0 + prow) * KDIM + pseg * 8;
    uint32_t soA[8], soB[8];
    #pragma unroll
    for (int j = 0; j < 8; ++j) {
        int rowA = prow + j * 16;
        soA[j] = rowA * 128 + ((pseg ^ (rowA & 7)) << 4);
        soB[j] = TM * 128 + rowA * 128 + ((pseg ^ (rowA & 7)) << 4);
    }

    // pAk/pBk always point at the NEXT k-chunk to be loaded.
    #define LOAD_STAGE_PART(sp_, j0_, j1_)                                        \
        _Pragma("unroll")                                                          \
        for (int j = (j0_); j < (j1_); ++j) {                                      \
            if (j < 8) cp_async16((sp_) + soA[j], pAk + (size_t)j * 16 * KDIM);    \
            else       cp_async16((sp_) + soB[j - 8], pBk + (size_t)(j - 8) * 16 * KDIM); \
        }

    // prologue: stages 0 and 1 (k-chunks 0 and 1)
    LOAD_STAGE_PART(sb + 0 * STAGE_BYTES, 0, 16); CP_COMMIT();
    pAk += KC; pBk += KC;
    LOAD_STAGE_PART(sb + 1 * STAGE_BYTES, 0, 16); CP_COMMIT();
    pAk += KC; pBk += KC;

    int la = (lane & 15);
    int khalf = lane >> 4;

    // fragment double buffers
    uint32_t afb[2][4][4];
    uint32_t bfb[2][8][2];

    #define LOAD_FRAGS(sa_, sB_, ks_, buf_) do {                                  \
        int seg_ = 2 * (ks_) + khalf;                                             \
        _Pragma("unroll")                                                          \
        for (int q = 0; q < 4; ++q) {                                             \
            int row_ = wn * 64 + q * 16 + la;                                     \
            uint32_t addr_ = (sB_) + row_ * 128 + ((seg_ ^ (row_ & 7)) << 4);     \
            uint32_t r0_, r1_, r2_, r3_;                                          \
            ldsm_x4(addr_, r0_, r1_, r2_, r3_);                                   \
            bfb[buf_][2 * q][0] = r0_;     bfb[buf_][2 * q][1] = r2_;             \
            bfb[buf_][2 * q + 1][0] = r1_; bfb[buf_][2 * q + 1][1] = r3_;         \
        }                                                                          \
        _Pragma("unroll")                                                          \
        for (int mt = 0; mt < 4; ++mt) {                                          \
            int row_ = wm * 64 + mt * 16 + la;                                    \
            uint32_t addr_ = (sa_) + row_ * 128 + ((seg_ ^ (row_ & 7)) << 4);     \
            ldsm_x4(addr_, afb[buf_][mt][0], afb[buf_][mt][1],                    \
                    afb[buf_][mt][2], afb[buf_][mt][3]);                          \
        }                                                                          \
    } while (0)

    // One pipeline iteration. CONS is a compile-time stage index; all SMEM
    // bases fold to sb + immediate. DOLOAD compile-time.
    #define ITER(CONS, DOLOAD) do {                                               \
        CP_WAIT1();                                                               \
        __syncthreads();                                                          \
        const uint32_t sa_c = sb + (CONS) * STAGE_BYTES;                          \
        const uint32_t sB_c = sa_c + TM * 128;                                    \
        const uint32_t sp_c = sb + (((CONS) + 2) % 3) * STAGE_BYTES;              \
        LOAD_FRAGS(sa_c, sB_c, 0, 0);                                             \
        _Pragma("unroll")                                                          \
        for (int ks = 0; ks < 4; ++ks) {                                          \
            int buf = ks & 1;                                                     \
            if (ks < 3) LOAD_FRAGS(sa_c, sB_c, ks + 1, buf ^ 1);                  \
            if (DOLOAD) LOAD_STAGE_PART(sp_c, ks * 4, ks * 4 + 4);                \
            _Pragma("unroll")                                                      \
            for (int mt = 0; mt < 4; ++mt)                                        \
                _Pragma("unroll")                                                  \
                for (int nb = 0; nb < 8; ++nb)                                    \
                    mma_16816(acc[mt][nb], afb[buf][mt],                          \
                              bfb[buf][nb][0], bfb[buf][nb][1]);                  \
        }                                                                          \
        CP_COMMIT();                                                              \
        if (DOLOAD) { pAk += KC; pBk += KC; }                                     \
    } while (0)

    // 60 loading iterations (it = 0..59), stage period 3
    #pragma unroll 1
    for (int blk = 0; blk < 20; ++blk) {
        ITER(0, true);
        ITER(1, true);
        ITER(2, true);
    }
    // tail: it = 60 (loads chunk 62), 61 (loads chunk 63), 62, 63 (drain)
    ITER(0, true);
    ITER(1, true);
    ITER(2, false);
    ITER(0, false);

    // ---------------- epilogue: bias + store ----------------
    float2 bv[8];
    #pragma unroll
    for (int nb = 0; nb < 8; ++nb) {
        int col = n0 + wn * 64 + nb * 8 + (lane & 3) * 2;
        bv[nb] = *reinterpret_cast<const float2*>(bias + col);
    }
    #pragma unroll
    for (int mt = 0; mt < 4; ++mt) {
        int gr = m0 + wm * 64 + mt * 16 + (lane >> 2);
        float* r0p = out + (size_t)gr * NDIM;
        float* r1p = r0p + 8 * (size_t)NDIM;
        #pragma unroll
        for (int nb = 0; nb < 8; ++nb) {
            int col = n0 + wn * 64 + nb * 8 + (lane & 3) * 2;
            float2 v0 = make_float2(acc[mt][nb][0] + bv[nb].x,
                                    acc[mt][nb][1] + bv[nb].y);
            float2 v1 = make_float2(acc[mt][nb][2] + bv[nb].x,
                                    acc[mt][nb][3] + bv[nb].y);
            *reinterpret_cast<float2*>(r0p + col) = v0;
            *reinterpret_cast<float2*>(r1p + col) = v1;
        }
    }
}

// ---------------- launch ----------------
extern "C" void kernel_launch(void* const* d_in, const int* in_sizes, int n_in,
                              void* d_out, int out_size) {
    const float* x    = (const float*)d_in[0];
    const float* w    = (const float*)d_in[1];
    const float* bias = (const float*)d_in[2];
    float* out = (float*)d_out;

    conv_x_kernel<<<(BATCH * (size_t)KDIM / 4) / 256, 256>>>((const float4*)x);
    conv_transpose_w_kernel<<<dim3(NDIM / 32, KDIM / 32), dim3(32, 8)>>>(w);

    cudaFuncSetAttribute(gemm_fp16_kernel,
                         cudaFuncAttributeMaxDynamicSharedMemorySize, SMEM_TOTAL);
    gemm_fp16_kernel<<<dim3(NDIM / TN, BATCH / TM), THREADS, SMEM_TOTAL>>>(bias, out);
}

// round 10
// speedup vs baseline: 1.0867x; 1.0399x over previous
#include <cuda_runtime.h>
#include <cuda_fp16.h>
#include <cstdint>

// out[B,N] = x[B,K] @ w[K,N] + bias[N]
// fp16 HMMA m16n8k16 f32-accum. CTA 128x128, 4 warps (2x2), warp tile 64x64,
// 2 CTAs/SM. Register double-buffered fragments; stage-unrolled mainloop;
// XOR-folded ldmatrix addresses; fused single-launch prepass.
#define BATCH 4096
#define KDIM  4096
#define NDIM  4096

#define TM 128
#define TN 128
#define KC 64          // K elements per stage (128 bytes fp16 per row)
#define STAGES 3
#define THREADS 128    // 4 warps: 2 (M) x 2 (N), warp tile 64x64
#define K_ITERS (KDIM / KC)   // 64

// ---------------- scratch (device globals: allocation-free) ----------------
__device__ __half g_x[(size_t)BATCH * KDIM];
__device__ __half g_w[(size_t)NDIM * KDIM];   // transposed: [n][k]

#define STAGE_BYTES ((TM + TN) * 128)       // 32768
#define SMEM_TOTAL  (STAGES * STAGE_BYTES)  // 98304 (x2 CTAs = 192KB/SM)

__device__ __forceinline__ uint32_t smem_u32(const void* p) {
    uint32_t a;
    asm("{ .reg .u64 t; cvta.to.shared.u64 t, %1; cvt.u32.u64 %0, t; }"
        : "=r"(a) : "l"(p));
    return a;
}

__device__ __forceinline__ void cp_async16(uint32_t smaddr, const void* gptr) {
    asm volatile("cp.async.cg.shared.global [%0], [%1], 16;\n"
                 :: "r"(smaddr), "l"(gptr));
}
#define CP_COMMIT() asm volatile("cp.async.commit_group;\n" ::: "memory")
#define CP_WAIT1()  asm volatile("cp.async.wait_group 1;\n" ::: "memory")

__device__ __forceinline__ void ldsm_x4(uint32_t addr, uint32_t& r0, uint32_t& r1,
                                        uint32_t& r2, uint32_t& r3) {
    asm volatile("ldmatrix.sync.aligned.m8n8.x4.shared.b16 {%0,%1,%2,%3}, [%4];"
                 : "=r"(r0), "=r"(r1), "=r"(r2), "=r"(r3) : "r"(addr));
}

__device__ __forceinline__ void mma_16816(float* c, const uint32_t* a,
                                          uint32_t b0, uint32_t b1) {
    asm volatile(
        "mma.sync.aligned.m16n8k16.row.col.f32.f16.f16.f32 "
        "{%0,%1,%2,%3}, {%4,%5,%6,%7}, {%8,%9}, {%0,%1,%2,%3};"
        : "+f"(c[0]), "+f"(c[1]), "+f"(c[2]), "+f"(c[3])
        : "r"(a[0]), "r"(a[1]), "r"(a[2]), "r"(a[3]), "r"(b0), "r"(b1));
}

// ---------------- fused prepass: x convert + w transpose/convert -----------
// blocks [0, 16384): convert x (float4 per thread)
// blocks [16384, 32768): 32x32 transpose tiles of w
#define XBLOCKS (BATCH * KDIM / 4 / 256)   // 16384
__global__ void __launch_bounds__(256) prepass_kernel(const float4* __restrict__ x,
                                                      const float* __restrict__ w) {
    __shared__ float tile[32][33];
    int bid = blockIdx.x;
    int tid = threadIdx.x;
    if (bid < XBLOCKS) {
        size_t i = (size_t)bid * 256 + tid;
        float4 v = x[i];
        __half2* xp = reinterpret_cast<__half2*>(g_x);
        xp[2 * i]     = __floats2half2_rn(v.x, v.y);
        xp[2 * i + 1] = __floats2half2_rn(v.z, v.w);
    } else {
        int r = bid - XBLOCKS;
        int o0 = (r & 127) * 32;   // output (N) tile
        int i0 = (r >> 7) * 32;    // input (K) tile
        int tx = tid & 31, ty = tid >> 5;
        #pragma unroll
        for (int rr = ty; rr < 32; rr += 8)
            tile[rr][tx] = w[(size_t)(i0 + rr) * NDIM + o0 + tx];
        __syncthreads();
        #pragma unroll
        for (int rr = ty; rr < 32; rr += 8) {
            float f = tile[tx][rr];  // = w[i0+tx][o0+rr]
            g_w[(size_t)(o0 + rr) * KDIM + i0 + tx] = __float2half_rn(f);
        }
    }
}

// ---------------- main GEMM ----------------
__global__ void __launch_bounds__(THREADS, 2)
gemm_fp16_kernel(const float* __restrict__ bias, float* __restrict__ out) {
    extern __shared__ char smem[];
    uint32_t sb = smem_u32(smem);
    int tid = threadIdx.x;
    int lane = tid & 31;
    int wid = tid >> 5;
    int wm = wid & 1;       // M warp group: 64 rows
    int wn = wid >> 1;      // N warp group: 64 cols
    int m0 = blockIdx.y * TM;
    int n0 = blockIdx.x * TN;

    float acc[4][8][4];     // [mt m16 tile][nb n8 tile][c0..c3]
    #pragma unroll
    for (int i = 0; i < 4; ++i)
        #pragma unroll
        for (int j = 0; j < 8; ++j)
            #pragma unroll
            for (int k = 0; k < 4; ++k) acc[i][j][k] = 0.f;

    // --- producer: per-thread fixed (row,seg); two pointers advance by KC ---
    int prow = tid >> 3;          // 0..15
    int pseg = tid & 7;
    const __half* pAk = g_x + (size_t)(m0 + prow) * KDIM + pseg * 8;
    const __half* pBk = g_w + (size_t)(n0 + prow) * KDIM + pseg * 8;
    uint32_t soA[8], soB[8];
    #pragma unroll
    for (int j = 0; j < 8; ++j) {
        int rowA = prow + j * 16;
        soA[j] = rowA * 128 + ((pseg ^ (rowA & 7)) << 4);
        soB[j] = TM * 128 + rowA * 128 + ((pseg ^ (rowA & 7)) << 4);
    }

    // pAk/pBk always point at the NEXT k-chunk to be loaded.
    #define LOAD_STAGE_PART(sp_, j0_, j1_)                                        \
        _Pragma("unroll")                                                          \
        for (int j = (j0_); j < (j1_); ++j) {                                      \
            if (j < 8) cp_async16((sp_) + soA[j], pAk + (size_t)j * 16 * KDIM);    \
            else       cp_async16((sp_) + soB[j - 8], pBk + (size_t)(j - 8) * 16 * KDIM); \
        }

    // prologue: stages 0 and 1 (k-chunks 0 and 1)
    LOAD_STAGE_PART(sb + 0 * STAGE_BYTES, 0, 16); CP_COMMIT();
    pAk += KC; pBk += KC;
    LOAD_STAGE_PART(sb + 1 * STAGE_BYTES, 0, 16); CP_COMMIT();
    pAk += KC; pBk += KC;

    int la = (lane & 15);
    int khalf = lane >> 4;

    // XOR-folded ldmatrix row bases: addr = stageBase + (base ^ (ks<<5))
    // base = row*128 + (((row&7) ^ khalf) << 4); seg field bits 4..6.
    uint32_t aBase[4], bBase[4];
    #pragma unroll
    for (int mt = 0; mt < 4; ++mt) {
        int row = wm * 64 + mt * 16 + la;
        aBase[mt] = row * 128 + (((row & 7) ^ khalf) << 4);
    }
    #pragma unroll
    for (int q = 0; q < 4; ++q) {
        int row = wn * 64 + q * 16 + la;
        bBase[q] = TM * 128 + row * 128 + (((row & 7) ^ khalf) << 4);
    }

    // fragment double buffers
    uint32_t afb[2][4][4];
    uint32_t bfb[2][8][2];

    #define LOAD_FRAGS(sa_, ks_, buf_) do {                                       \
        _Pragma("unroll")                                                          \
        for (int q = 0; q < 4; ++q) {                                             \
            uint32_t addr_ = (sa_) + (bBase[q] ^ ((ks_) << 5));                   \
            uint32_t r0_, r1_, r2_, r3_;                                          \
            ldsm_x4(addr_, r0_, r1_, r2_, r3_);                                   \
            bfb[buf_][2 * q][0] = r0_;     bfb[buf_][2 * q][1] = r2_;             \
            bfb[buf_][2 * q + 1][0] = r1_; bfb[buf_][2 * q + 1][1] = r3_;         \
        }                                                                          \
        _Pragma("unroll")                                                          \
        for (int mt = 0; mt < 4; ++mt) {                                          \
            uint32_t addr_ = (sa_) + (aBase[mt] ^ ((ks_) << 5));                  \
            ldsm_x4(addr_, afb[buf_][mt][0], afb[buf_][mt][1],                    \
                    afb[buf_][mt][2], afb[buf_][mt][3]);                          \
        }                                                                          \
    } while (0)

    // One pipeline iteration. CONS compile-time; SMEM bases fold to immediates.
    #define ITER(CONS, DOLOAD) do {                                               \
        CP_WAIT1();                                                               \
        __syncthreads();                                                          \
        const uint32_t sa_c = sb + (CONS) * STAGE_BYTES;                          \
        const uint32_t sp_c = sb + (((CONS) + 2) % 3) * STAGE_BYTES;              \
        LOAD_FRAGS(sa_c, 0, 0);                                                   \
        _Pragma("unroll")                                                          \
        for (int ks = 0; ks < 4; ++ks) {                                          \
            int buf = ks & 1;                                                     \
            if (ks < 3) LOAD_FRAGS(sa_c, ks + 1, buf ^ 1);                        \
            if (DOLOAD) LOAD_STAGE_PART(sp_c, ks * 4, ks * 4 + 4);                \
            _Pragma("unroll")                                                      \
            for (int mt = 0; mt < 4; ++mt)                                        \
                _Pragma("unroll")                                                  \
                for (int nb = 0; nb < 8; ++nb)                                    \
                    mma_16816(acc[mt][nb], afb[buf][mt],                          \
                              bfb[buf][nb][0], bfb[buf][nb][1]);                  \
        }                                                                          \
        CP_COMMIT();                                                              \
        if (DOLOAD) { pAk += KC; pBk += KC; }                                     \
    } while (0)

    // 60 loading iterations (it = 0..59), stage period 3
    #pragma unroll 1
    for (int blk = 0; blk < 20; ++blk) {
        ITER(0, true);
        ITER(1, true);
        ITER(2, true);
    }
    // tail: it = 60 (loads chunk 62), 61 (loads chunk 63), 62, 63 (drain)
    ITER(0, true);
    ITER(1, true);
    ITER(2, false);
    ITER(0, false);

    // ---------------- epilogue: bias + store ----------------
    float2 bv[8];
    #pragma unroll
    for (int nb = 0; nb < 8; ++nb) {
        int col = n0 + wn * 64 + nb * 8 + (lane & 3) * 2;
        bv[nb] = *reinterpret_cast<const float2*>(bias + col);
    }
    #pragma unroll
    for (int mt = 0; mt < 4; ++mt) {
        int gr = m0 + wm * 64 + mt * 16 + (lane >> 2);
        float* r0p = out + (size_t)gr * NDIM;
        float* r1p = r0p + 8 * (size_t)NDIM;
        #pragma unroll
        for (int nb = 0; nb < 8; ++nb) {
            int col = n0 + wn * 64 + nb * 8 + (lane & 3) * 2;
            float2 v0 = make_float2(acc[mt][nb][0] + bv[nb].x,
                                    acc[mt][nb][1] + bv[nb].y);
            float2 v1 = make_float2(acc[mt][nb][2] + bv[nb].x,
                                    acc[mt][nb][3] + bv[nb].y);
            *reinterpret_cast<float2*>(r0p + col) = v0;
            *reinterpret_cast<float2*>(r1p + col) = v1;
        }
    }
}

// ---------------- launch ----------------
extern "C" void kernel_launch(void* const* d_in, const int* in_sizes, int n_in,
                              void* d_out, int out_size) {
    const float* x    = (const float*)d_in[0];
    const float* w    = (const float*)d_in[1];
    const float* bias = (const float*)d_in[2];
    float* out = (float*)d_out;

    prepass_kernel<<<XBLOCKS + (NDIM / 32) * (KDIM / 32), 256>>>((const float4*)x, w);

    cudaFuncSetAttribute(gemm_fp16_kernel,
                         cudaFuncAttributeMaxDynamicSharedMemorySize, SMEM_TOTAL);
    gemm_fp16_kernel<<<dim3(NDIM / TN, BATCH / TM), THREADS, SMEM_TOTAL>>>(bias, out);
}